// round 1
// baseline (speedup 1.0000x reference)
#include <cuda_runtime.h>

// GCNConv on GB300: out = relu(D^-1/2 (A+I) D^-1/2 (X W) + b), edge-weighted.
// Decomposition:
//   deg[i] = 1 + sum_{e: col=i} w[e];  dis = rsqrt(deg)
//   xs[i]  = dis[i] * (X[i] @ W)                       (GEMM, fused scale)
//   acc[c] += w_e * xs[r]  for each edge (r,c)          (vector red.global.add)
//   out[i] = relu(dis[i]*(acc[i] + xs[i]) + b)          (self-loop folded in)

constexpr int N_NODES = 100000;
constexpr int N_EDGES = 1600000;
constexpr int F_IN    = 128;
constexpr int F_OUT   = 64;

// Scratch (no allocations allowed): ~51.3 MB of __device__ globals.
__device__ __align__(16) float g_deg[N_NODES];
__device__ __align__(16) float g_dis[N_NODES];
__device__ __align__(16) float g_xs[(size_t)N_NODES * F_OUT];
__device__ __align__(16) float g_acc[(size_t)N_NODES * F_OUT];

// ---------------------------------------------------------------------------
// K0: zero acc, set deg = 1 (self-loop weight).
__global__ void k_init() {
    int i = blockIdx.x * blockDim.x + threadIdx.x;
    if (i < N_NODES * F_OUT / 4)
        reinterpret_cast<float4*>(g_acc)[i] = make_float4(0.f, 0.f, 0.f, 0.f);
    if (i < N_NODES)
        g_deg[i] = 1.0f;
}

// ---------------------------------------------------------------------------
// K1: scatter edge weights into degrees at targets.
__global__ void k_deg(const int* __restrict__ col, const float* __restrict__ w) {
    int e = blockIdx.x * blockDim.x + threadIdx.x;
    if (e < N_EDGES)
        atomicAdd(&g_deg[col[e]], w[e]);
}

// ---------------------------------------------------------------------------
// K2: xs = dis * (X @ W). W (128x64 fp32 = 32KB) in shared; X tiled 16 nodes
// at a time into shared; each thread computes a float4 of outputs for one node.
constexpr int GEMM_NPB = 128;   // nodes per block
constexpr int GEMM_TPB = 256;   // threads per block

__global__ __launch_bounds__(GEMM_TPB)
void k_gemm(const float* __restrict__ X, const float* __restrict__ W) {
    __shared__ float sW[F_IN * F_OUT];   // 32 KB
    __shared__ float sX[16 * F_IN];      // 8 KB

    // Load W once per block (coalesced float4).
    for (int i = threadIdx.x; i < F_IN * F_OUT / 4; i += GEMM_TPB)
        reinterpret_cast<float4*>(sW)[i] =
            reinterpret_cast<const float4*>(W)[i];

    const int base = blockIdx.x * GEMM_NPB;
    const int local = threadIdx.x >> 4;   // 0..15 node within tile
    const int jq    = threadIdx.x & 15;   // output quad: features 4*jq..4*jq+3

    for (int t = 0; t < GEMM_NPB; t += 16) {
        __syncthreads();
        // Load 16 node rows (16 x 128 fp32 = 8 KB) into shared.
        const int n0 = base + t;
        for (int i = threadIdx.x; i < 16 * F_IN / 4; i += GEMM_TPB) {
            int node = n0 + (i >> 5);              // F_IN/4 == 32 float4 per row
            float4 v = make_float4(0.f, 0.f, 0.f, 0.f);
            if (node < N_NODES)
                v = reinterpret_cast<const float4*>(X)[(size_t)node * (F_IN / 4) + (i & 31)];
            reinterpret_cast<float4*>(sX)[i] = v;
        }
        __syncthreads();

        const int node = n0 + local;
        float4 acc = make_float4(0.f, 0.f, 0.f, 0.f);
        #pragma unroll
        for (int k = 0; k < F_IN; k++) {
            float  x = sX[local * F_IN + k];                       // broadcast
            float4 w = reinterpret_cast<float4*>(sW)[k * 16 + jq]; // coalesced
            acc.x = fmaf(x, w.x, acc.x);
            acc.y = fmaf(x, w.y, acc.y);
            acc.z = fmaf(x, w.z, acc.z);
            acc.w = fmaf(x, w.w, acc.w);
        }
        if (node < N_NODES) {
            float d = rsqrtf(g_deg[node]);   // deg >= 1, always > 0
            if (jq == 0) g_dis[node] = d;
            acc.x *= d; acc.y *= d; acc.z *= d; acc.w *= d;
            reinterpret_cast<float4*>(g_xs)[(size_t)node * 16 + jq] = acc;
        }
    }
}

// ---------------------------------------------------------------------------
// K3: edge aggregation. 16 lanes per edge; each lane handles a float4 slice.
// acc[c*64 + 4l .. +3] += w_e * xs[r*64 + 4l .. +3] via red.global.add.v4.f32.
// Both xs (25.6MB) and acc (25.6MB) fit in L2, so this is L2-resident traffic.
__global__ __launch_bounds__(256)
void k_edge(const int* __restrict__ row, const int* __restrict__ col,
            const float* __restrict__ w) {
    int t = blockIdx.x * blockDim.x + threadIdx.x;
    int e = t >> 4;
    int l = t & 15;
    if (e >= N_EDGES) return;
    int   r  = __ldg(row + e);
    int   c  = __ldg(col + e);
    float we = __ldg(w + e);
    float4 v = reinterpret_cast<const float4*>(g_xs)[(size_t)r * 16 + l];
    v.x *= we; v.y *= we; v.z *= we; v.w *= we;
    float* p = &g_acc[(size_t)c * F_OUT + l * 4];
    asm volatile("red.global.add.v4.f32 [%0], {%1, %2, %3, %4};"
                 :: "l"(p), "f"(v.x), "f"(v.y), "f"(v.z), "f"(v.w)
                 : "memory");
}

// ---------------------------------------------------------------------------
// K4: out = relu(dis * (acc + xs) + b).  One thread per float4.
__global__ void k_out(const float* __restrict__ b, float* __restrict__ out) {
    int i = blockIdx.x * blockDim.x + threadIdx.x;   // over N*16 float4s
    if (i >= N_NODES * 16) return;
    int node = i >> 4;
    int jq   = i & 15;
    float  d  = g_dis[node];
    float4 a  = reinterpret_cast<float4*>(g_acc)[i];
    float4 x  = reinterpret_cast<float4*>(g_xs)[i];
    float4 bb = reinterpret_cast<const float4*>(b)[jq];
    float4 o;
    o.x = fmaxf(fmaf(d, a.x + x.x, bb.x), 0.f);
    o.y = fmaxf(fmaf(d, a.y + x.y, bb.y), 0.f);
    o.z = fmaxf(fmaf(d, a.z + x.z, bb.z), 0.f);
    o.w = fmaxf(fmaf(d, a.w + x.w, bb.w), 0.f);
    reinterpret_cast<float4*>(out)[i] = o;
}

// ---------------------------------------------------------------------------
extern "C" void kernel_launch(void* const* d_in, const int* in_sizes, int n_in,
                              void* d_out, int out_size) {
    const float* X  = (const float*)d_in[0];            // [N, 128]
    const int*   ei = (const int*)d_in[1];              // [2, E]
    const float* w  = (const float*)d_in[2];            // [E]
    const float* W  = (const float*)d_in[3];            // [128, 64]
    const float* b  = (const float*)d_in[4];            // [64]
    float* out = (float*)d_out;                         // [N, 64]

    const int* row = ei;                // edge_index[0] = sources
    const int* col = ei + N_EDGES;      // edge_index[1] = targets

    {   // K0: init (covers max(N*16 float4s, N_NODES) threads)
        int total = N_NODES * F_OUT / 4;   // 1.6M
        k_init<<<(total + 255) / 256, 256>>>();
    }
    {   // K1: degrees
        k_deg<<<(N_EDGES + 255) / 256, 256>>>(col, w);
    }
    {   // K2: GEMM + dis scale
        int grid = (N_NODES + GEMM_NPB - 1) / GEMM_NPB;
        k_gemm<<<grid, GEMM_TPB>>>(X, W);
    }
    {   // K3: edge aggregation, 16 threads per edge
        long long threads = (long long)N_EDGES * 16;
        k_edge<<<(int)((threads + 255) / 256), 256>>>(row, col, w);
    }
    {   // K4: epilogue
        int total = N_NODES * 16;
        k_out<<<(total + 255) / 256, 256>>>(b, out);
    }
}

// round 3
// speedup vs baseline: 1.2339x; 1.2339x over previous
#include <cuda_runtime.h>

// GCNConv on GB300: out = relu(D^-1/2 (A+I) D^-1/2 (X W) + b), edge-weighted.
//   deg[i] = sum_{e: col=i} w[e];  dis = rsqrt(deg + 1)       (self-loop)
//   xs[i]  = dis[i] * (X[i] @ W)            (f32x2 register-blocked GEMM)
//   acc[c] += w_e * xs[r]                   (red.global.add.v4.f32, L2-resident)
//   out[i] = relu(dis[i]*(acc[i] + xs[i]) + b)

constexpr int N_NODES = 100000;
constexpr int N_EDGES = 1600000;
constexpr int F_IN    = 128;
constexpr int F_OUT   = 64;

typedef unsigned long long ull;

__device__ __align__(16) float g_deg[N_NODES];
__device__ __align__(16) float g_dis[N_NODES];
__device__ __align__(16) float g_xs[(size_t)N_NODES * F_OUT];
__device__ __align__(16) float g_acc[(size_t)N_NODES * F_OUT];

__device__ __forceinline__ ull pack2(float x) {
    ull r; asm("mov.b64 %0, {%1, %1};" : "=l"(r) : "f"(x)); return r;
}
__device__ __forceinline__ void fma2(ull& d, ull a, ull b) {
    asm("fma.rn.f32x2 %0, %1, %2, %0;" : "+l"(d) : "l"(a), "l"(b));
}
__device__ __forceinline__ ull mul2(ull a, ull b) {
    ull r; asm("mul.rn.f32x2 %0, %1, %2;" : "=l"(r) : "l"(a), "l"(b)); return r;
}

// ---------------------------------------------------------------------------
// K0: zero acc and deg.
__global__ void k_init() {
    int i = blockIdx.x * blockDim.x + threadIdx.x;
    if (i < N_NODES * F_OUT / 4)
        reinterpret_cast<float4*>(g_acc)[i] = make_float4(0.f, 0.f, 0.f, 0.f);
    if (i < N_NODES)
        g_deg[i] = 0.0f;
}

// ---------------------------------------------------------------------------
// K1: scatter edge weights into degrees at targets (RED, no return).
__global__ void k_deg(const int* __restrict__ col, const float* __restrict__ w) {
    int e = blockIdx.x * blockDim.x + threadIdx.x;
    if (e < N_EDGES)
        atomicAdd(&g_deg[col[e]], w[e]);
}

// ---------------------------------------------------------------------------
// K2: xs = dis * (X @ W), register-blocked f32x2 GEMM.
// 256 threads, 128 nodes/block. Thread = (g = tid&7 -> features 8g..8g+7,
// slot = tid>>3 -> local nodes slot*4..slot*4+3). Accum = 4 nodes x 4 f32x2.
// W (32KB) resident in shared; X staged in 32-wide K chunks with XOR swizzle
// sX[node][(k^node)&31] -> conflict-free stores AND loads (verified per-lane).
constexpr int GEMM_TPB = 256;
constexpr int NPB      = 128;   // nodes per block
constexpr int KC       = 32;    // K chunk

__global__ __launch_bounds__(GEMM_TPB)
void k_gemm(const float* __restrict__ X, const float* __restrict__ W) {
    __shared__ float sW[F_IN * F_OUT];   // 32 KB
    __shared__ float sX[NPB * KC];       // 16 KB (48 KB total)

    const int tid  = threadIdx.x;
    const int g    = tid & 7;            // feature group
    const int slot = tid >> 3;           // 0..31
    const int nb   = blockIdx.x * NPB;
    const int ln0  = slot * 4;           // first local node

    for (int i = tid; i < F_IN * F_OUT / 4; i += GEMM_TPB)
        reinterpret_cast<float4*>(sW)[i] = reinterpret_cast<const float4*>(W)[i];

    ull acc[4][4];
    #pragma unroll
    for (int i = 0; i < 4; i++)
        #pragma unroll
        for (int j = 0; j < 4; j++) acc[i][j] = 0ull;

    for (int c = 0; c < F_IN / KC; c++) {
        __syncthreads();
        // Stage X chunk: 128 nodes x 32 k, swizzled.
        for (int i = tid; i < NPB * KC / 4; i += GEMM_TPB) {
            int node = i >> 3;            // KC/4 = 8 float4 per node
            int kq   = i & 7;
            float4 v = make_float4(0.f, 0.f, 0.f, 0.f);
            int gn = nb + node;
            if (gn < N_NODES)
                v = reinterpret_cast<const float4*>(X)[(size_t)gn * (F_IN / 4) + c * 8 + kq];
            int k0 = kq * 4;
            sX[node * KC + (((k0 + 0) ^ node) & 31)] = v.x;
            sX[node * KC + (((k0 + 1) ^ node) & 31)] = v.y;
            sX[node * KC + (((k0 + 2) ^ node) & 31)] = v.z;
            sX[node * KC + (((k0 + 3) ^ node) & 31)] = v.w;
        }
        __syncthreads();

        #pragma unroll
        for (int kk = 0; kk < KC; kk++) {
            int row = c * KC + kk;
            // w[row][8g..8g+7] as 4 f32x2 (two 16B shared loads, broadcast x8)
            ulonglong2 wa = reinterpret_cast<ulonglong2*>(sW)[row * 16 + g * 2];
            ulonglong2 wb = reinterpret_cast<ulonglong2*>(sW)[row * 16 + g * 2 + 1];
            #pragma unroll
            for (int i = 0; i < 4; i++) {
                int ln = ln0 + i;
                float x = sX[ln * KC + ((kk ^ ln) & 31)];
                ull xx = pack2(x);
                fma2(acc[i][0], xx, wa.x);
                fma2(acc[i][1], xx, wa.y);
                fma2(acc[i][2], xx, wb.x);
                fma2(acc[i][3], xx, wb.y);
            }
        }
    }

    // Epilogue: scale by dis = rsqrt(deg+1), store xs (+ dis once per node).
    // NOTE: a g_xs row (64 floats) is 16 ulonglong2 -> row stride is gn*16.
    #pragma unroll
    for (int i = 0; i < 4; i++) {
        int gn = nb + ln0 + i;
        if (gn < N_NODES) {
            float d = rsqrtf(g_deg[gn] + 1.0f);
            if (g == 0) g_dis[gn] = d;
            ull dd = pack2(d);
            ulonglong2 o0, o1;
            o0.x = mul2(acc[i][0], dd); o0.y = mul2(acc[i][1], dd);
            o1.x = mul2(acc[i][2], dd); o1.y = mul2(acc[i][3], dd);
            reinterpret_cast<ulonglong2*>(g_xs)[(size_t)gn * 16 + g * 2]     = o0;
            reinterpret_cast<ulonglong2*>(g_xs)[(size_t)gn * 16 + g * 2 + 1] = o1;
        }
    }
}

// ---------------------------------------------------------------------------
// K3: edge aggregation. 16 lanes x 2 edges per thread (2 gathers in flight to
// cover L2 latency). acc[c] += w_e * xs[r] via red.global.add.v4.f32.
__global__ __launch_bounds__(256)
void k_edge(const int* __restrict__ row, const int* __restrict__ col,
            const float* __restrict__ w) {
    int t = blockIdx.x * blockDim.x + threadIdx.x;
    int e0 = (t >> 4) * 2;
    int l  = t & 15;
    if (e0 >= N_EDGES) return;
    int e1 = e0 + 1;

    int   r0 = __ldg(row + e0),  r1 = __ldg(row + e1);
    int   c0 = __ldg(col + e0),  c1 = __ldg(col + e1);
    float w0 = __ldg(w + e0),    w1 = __ldg(w + e1);

    float4 v0 = reinterpret_cast<const float4*>(g_xs)[(size_t)r0 * 16 + l];
    float4 v1 = reinterpret_cast<const float4*>(g_xs)[(size_t)r1 * 16 + l];
    v0.x *= w0; v0.y *= w0; v0.z *= w0; v0.w *= w0;
    v1.x *= w1; v1.y *= w1; v1.z *= w1; v1.w *= w1;

    float* p0 = &g_acc[(size_t)c0 * F_OUT + l * 4];
    float* p1 = &g_acc[(size_t)c1 * F_OUT + l * 4];
    asm volatile("red.global.add.v4.f32 [%0], {%1, %2, %3, %4};"
                 :: "l"(p0), "f"(v0.x), "f"(v0.y), "f"(v0.z), "f"(v0.w) : "memory");
    asm volatile("red.global.add.v4.f32 [%0], {%1, %2, %3, %4};"
                 :: "l"(p1), "f"(v1.x), "f"(v1.y), "f"(v1.z), "f"(v1.w) : "memory");
}

// ---------------------------------------------------------------------------
// K4: out = relu(dis * (acc + xs) + b).
__global__ void k_out(const float* __restrict__ b, float* __restrict__ out) {
    int i = blockIdx.x * blockDim.x + threadIdx.x;   // over N*16 float4s
    if (i >= N_NODES * 16) return;
    int node = i >> 4;
    int jq   = i & 15;
    float  d  = g_dis[node];
    float4 a  = reinterpret_cast<float4*>(g_acc)[i];
    float4 x  = reinterpret_cast<float4*>(g_xs)[i];
    float4 bb = reinterpret_cast<const float4*>(b)[jq];
    float4 o;
    o.x = fmaxf(fmaf(d, a.x + x.x, bb.x), 0.f);
    o.y = fmaxf(fmaf(d, a.y + x.y, bb.y), 0.f);
    o.z = fmaxf(fmaf(d, a.z + x.z, bb.z), 0.f);
    o.w = fmaxf(fmaf(d, a.w + x.w, bb.w), 0.f);
    reinterpret_cast<float4*>(out)[i] = o;
}

// ---------------------------------------------------------------------------
extern "C" void kernel_launch(void* const* d_in, const int* in_sizes, int n_in,
                              void* d_out, int out_size) {
    const float* X  = (const float*)d_in[0];            // [N, 128]
    const int*   ei = (const int*)d_in[1];              // [2, E]
    const float* w  = (const float*)d_in[2];            // [E]
    const float* W  = (const float*)d_in[3];            // [128, 64]
    const float* b  = (const float*)d_in[4];            // [64]
    float* out = (float*)d_out;                         // [N, 64]

    const int* row = ei;                // sources
    const int* col = ei + N_EDGES;      // targets

    {   int total = N_NODES * F_OUT / 4;
        k_init<<<(total + 255) / 256, 256>>>(); }
    {   k_deg<<<(N_EDGES + 255) / 256, 256>>>(col, w); }
    {   int grid = (N_NODES + NPB - 1) / NPB;
        k_gemm<<<grid, GEMM_TPB>>>(X, W); }
    {   long long threads = (long long)(N_EDGES / 2) * 16;
        k_edge<<<(int)((threads + 255) / 256), 256>>>(row, col, w); }
    {   int total = N_NODES * 16;
        k_out<<<(total + 255) / 256, 256>>>(b, out); }
}

// round 4
// speedup vs baseline: 1.3186x; 1.0687x over previous
#include <cuda_runtime.h>

// GCNConv on GB300: out = relu(D^-1/2 (A+I) D^-1/2 (X W) + b), edge-weighted.
// R4: CSR-on-the-fly gather-reduce (no scatter atomics on features).
//   deg[c] = sum_{e: col=c} w[e];  cnt[c] = #edges into c;  epos[e] = rank
//   off[c] = segment base (atomic cursor; order irrelevant)
//   sw[off[c]+epos[e]] = (row[e], w[e])        packed int2
//   xs[i]  = rsqrt(deg[i]+1) * (X[i] @ W)      f32x2 register-blocked GEMM
//   out[c] = relu(dis[c] * (sum_j w_j*xs[src_j] + xs[c]) + b)   fused epilogue

constexpr int N_NODES = 100000;
constexpr int N_EDGES = 1600000;
constexpr int F_IN    = 128;
constexpr int F_OUT   = 64;

typedef unsigned long long ull;

__device__ __align__(16) float g_deg[N_NODES];
__device__ __align__(16) float g_dis[N_NODES];
__device__ __align__(16) float g_xs[(size_t)N_NODES * F_OUT];
__device__ int  g_cnt[N_NODES];
__device__ int  g_off[N_NODES];
__device__ int  g_epos[N_EDGES];
__device__ __align__(16) int2 g_sw[N_EDGES];
__device__ int  g_cursor;

__device__ __forceinline__ ull pack2(float x) {
    ull r; asm("mov.b64 %0, {%1, %1};" : "=l"(r) : "f"(x)); return r;
}
__device__ __forceinline__ void fma2(ull& d, ull a, ull b) {
    asm("fma.rn.f32x2 %0, %1, %2, %0;" : "+l"(d) : "l"(a), "l"(b));
}
__device__ __forceinline__ ull mul2(ull a, ull b) {
    ull r; asm("mul.rn.f32x2 %0, %1, %2;" : "=l"(r) : "l"(a), "l"(b)); return r;
}

// ---------------------------------------------------------------------------
// K0: zero deg, cnt, cursor.
__global__ void k_init() {
    int i = blockIdx.x * blockDim.x + threadIdx.x;
    if (i < N_NODES) { g_deg[i] = 0.0f; g_cnt[i] = 0; }
    if (i == 0) g_cursor = 0;
}

// ---------------------------------------------------------------------------
// K1: weighted degree + per-target edge count + per-edge rank.
__global__ void k_deg(const int* __restrict__ col, const float* __restrict__ w) {
    int e = blockIdx.x * blockDim.x + threadIdx.x;
    if (e >= N_EDGES) return;
    int c = __ldg(col + e);
    atomicAdd(&g_deg[c], __ldg(w + e));
    g_epos[e] = atomicAdd(&g_cnt[c], 1);
}

// ---------------------------------------------------------------------------
// K2: segment base per node via global cursor (order of segments irrelevant).
__global__ void k_alloc() {
    int i = blockIdx.x * blockDim.x + threadIdx.x;
    if (i < N_NODES)
        g_off[i] = atomicAdd(&g_cursor, g_cnt[i]);
}

// ---------------------------------------------------------------------------
// K3: scatter packed (src, weight) into the target's contiguous segment.
__global__ void k_scatter(const int* __restrict__ row, const int* __restrict__ col,
                          const float* __restrict__ w) {
    int e = blockIdx.x * blockDim.x + threadIdx.x;
    if (e >= N_EDGES) return;
    int c = __ldg(col + e);
    int idx = g_off[c] + g_epos[e];
    g_sw[idx] = make_int2(__ldg(row + e), __float_as_int(__ldg(w + e)));
}

// ---------------------------------------------------------------------------
// K4: xs = dis * (X @ W), f32x2 register-blocked GEMM (unchanged from R3).
constexpr int GEMM_TPB = 256;
constexpr int NPB      = 128;
constexpr int KC       = 32;

__global__ __launch_bounds__(GEMM_TPB)
void k_gemm(const float* __restrict__ X, const float* __restrict__ W) {
    __shared__ float sW[F_IN * F_OUT];   // 32 KB
    __shared__ float sX[NPB * KC];       // 16 KB

    const int tid  = threadIdx.x;
    const int g    = tid & 7;
    const int slot = tid >> 3;
    const int nb   = blockIdx.x * NPB;
    const int ln0  = slot * 4;

    for (int i = tid; i < F_IN * F_OUT / 4; i += GEMM_TPB)
        reinterpret_cast<float4*>(sW)[i] = reinterpret_cast<const float4*>(W)[i];

    ull acc[4][4];
    #pragma unroll
    for (int i = 0; i < 4; i++)
        #pragma unroll
        for (int j = 0; j < 4; j++) acc[i][j] = 0ull;

    for (int c = 0; c < F_IN / KC; c++) {
        __syncthreads();
        for (int i = tid; i < NPB * KC / 4; i += GEMM_TPB) {
            int node = i >> 3;
            int kq   = i & 7;
            float4 v = make_float4(0.f, 0.f, 0.f, 0.f);
            int gn = nb + node;
            if (gn < N_NODES)
                v = reinterpret_cast<const float4*>(X)[(size_t)gn * (F_IN / 4) + c * 8 + kq];
            int k0 = kq * 4;
            sX[node * KC + (((k0 + 0) ^ node) & 31)] = v.x;
            sX[node * KC + (((k0 + 1) ^ node) & 31)] = v.y;
            sX[node * KC + (((k0 + 2) ^ node) & 31)] = v.z;
            sX[node * KC + (((k0 + 3) ^ node) & 31)] = v.w;
        }
        __syncthreads();

        #pragma unroll
        for (int kk = 0; kk < KC; kk++) {
            int row = c * KC + kk;
            ulonglong2 wa = reinterpret_cast<ulonglong2*>(sW)[row * 16 + g * 2];
            ulonglong2 wb = reinterpret_cast<ulonglong2*>(sW)[row * 16 + g * 2 + 1];
            #pragma unroll
            for (int i = 0; i < 4; i++) {
                int ln = ln0 + i;
                float x = sX[ln * KC + ((kk ^ ln) & 31)];
                ull xx = pack2(x);
                fma2(acc[i][0], xx, wa.x);
                fma2(acc[i][1], xx, wa.y);
                fma2(acc[i][2], xx, wb.x);
                fma2(acc[i][3], xx, wb.y);
            }
        }
    }

    #pragma unroll
    for (int i = 0; i < 4; i++) {
        int gn = nb + ln0 + i;
        if (gn < N_NODES) {
            float d = rsqrtf(g_deg[gn] + 1.0f);
            if (g == 0) g_dis[gn] = d;
            ull dd = pack2(d);
            ulonglong2 o0, o1;
            o0.x = mul2(acc[i][0], dd); o0.y = mul2(acc[i][1], dd);
            o1.x = mul2(acc[i][2], dd); o1.y = mul2(acc[i][3], dd);
            reinterpret_cast<ulonglong2*>(g_xs)[(size_t)gn * 16 + g * 2]     = o0;
            reinterpret_cast<ulonglong2*>(g_xs)[(size_t)gn * 16 + g * 2 + 1] = o1;
        }
    }
}

// ---------------------------------------------------------------------------
// K5: gather-reduce + fused epilogue. Half-warp (16 lanes x float4) per node.
// acc = sum_j w_j * xs[src_j] (register accumulation, unroll-4 for MLP),
// out = relu(dis * (acc + xs[node]) + b).
__global__ __launch_bounds__(256)
void k_agg(const float* __restrict__ b, float* __restrict__ out) {
    int t = blockIdx.x * blockDim.x + threadIdx.x;
    int node = t >> 4;
    int l    = t & 15;
    if (node >= N_NODES) return;

    const int off = g_off[node];
    const int cnt = g_cnt[node];
    const float4* xs4 = reinterpret_cast<const float4*>(g_xs);

    float4 acc = make_float4(0.f, 0.f, 0.f, 0.f);
    int j = 0;
    for (; j + 4 <= cnt; j += 4) {
        int2 e0 = __ldg(&g_sw[off + j]);
        int2 e1 = __ldg(&g_sw[off + j + 1]);
        int2 e2 = __ldg(&g_sw[off + j + 2]);
        int2 e3 = __ldg(&g_sw[off + j + 3]);
        float4 v0 = __ldg(&xs4[(size_t)e0.x * 16 + l]);
        float4 v1 = __ldg(&xs4[(size_t)e1.x * 16 + l]);
        float4 v2 = __ldg(&xs4[(size_t)e2.x * 16 + l]);
        float4 v3 = __ldg(&xs4[(size_t)e3.x * 16 + l]);
        float w0 = __int_as_float(e0.y), w1 = __int_as_float(e1.y);
        float w2 = __int_as_float(e2.y), w3 = __int_as_float(e3.y);
        acc.x = fmaf(w0, v0.x, acc.x); acc.y = fmaf(w0, v0.y, acc.y);
        acc.z = fmaf(w0, v0.z, acc.z); acc.w = fmaf(w0, v0.w, acc.w);
        acc.x = fmaf(w1, v1.x, acc.x); acc.y = fmaf(w1, v1.y, acc.y);
        acc.z = fmaf(w1, v1.z, acc.z); acc.w = fmaf(w1, v1.w, acc.w);
        acc.x = fmaf(w2, v2.x, acc.x); acc.y = fmaf(w2, v2.y, acc.y);
        acc.z = fmaf(w2, v2.z, acc.z); acc.w = fmaf(w2, v2.w, acc.w);
        acc.x = fmaf(w3, v3.x, acc.x); acc.y = fmaf(w3, v3.y, acc.y);
        acc.z = fmaf(w3, v3.z, acc.z); acc.w = fmaf(w3, v3.w, acc.w);
    }
    for (; j < cnt; j++) {
        int2 e = __ldg(&g_sw[off + j]);
        float4 v = __ldg(&xs4[(size_t)e.x * 16 + l]);
        float we = __int_as_float(e.y);
        acc.x = fmaf(we, v.x, acc.x); acc.y = fmaf(we, v.y, acc.y);
        acc.z = fmaf(we, v.z, acc.z); acc.w = fmaf(we, v.w, acc.w);
    }

    float  d  = g_dis[node];
    float4 x  = xs4[(size_t)node * 16 + l];
    float4 bb = reinterpret_cast<const float4*>(b)[l];
    float4 o;
    o.x = fmaxf(fmaf(d, acc.x + x.x, bb.x), 0.f);
    o.y = fmaxf(fmaf(d, acc.y + x.y, bb.y), 0.f);
    o.z = fmaxf(fmaf(d, acc.z + x.z, bb.z), 0.f);
    o.w = fmaxf(fmaf(d, acc.w + x.w, bb.w), 0.f);
    reinterpret_cast<float4*>(out)[(size_t)node * 16 + l] = o;
}

// ---------------------------------------------------------------------------
extern "C" void kernel_launch(void* const* d_in, const int* in_sizes, int n_in,
                              void* d_out, int out_size) {
    const float* X  = (const float*)d_in[0];            // [N, 128]
    const int*   ei = (const int*)d_in[1];              // [2, E]
    const float* w  = (const float*)d_in[2];            // [E]
    const float* W  = (const float*)d_in[3];            // [128, 64]
    const float* b  = (const float*)d_in[4];            // [64]
    float* out = (float*)d_out;                         // [N, 64]

    const int* row = ei;                // sources
    const int* col = ei + N_EDGES;      // targets

    k_init   <<<(N_NODES + 255) / 256, 256>>>();
    k_deg    <<<(N_EDGES + 255) / 256, 256>>>(col, w);
    k_alloc  <<<(N_NODES + 255) / 256, 256>>>();
    k_scatter<<<(N_EDGES + 255) / 256, 256>>>(row, col, w);
    {   int grid = (N_NODES + NPB - 1) / NPB;
        k_gemm<<<grid, GEMM_TPB>>>(X, W); }
    {   long long threads = (long long)N_NODES * 16;
        k_agg<<<(int)((threads + 255) / 256), 256>>>(b, out); }
}